// round 7
// baseline (speedup 1.0000x reference)
#include <cuda_runtime.h>
#include <cuda_bf16.h>
#include <math.h>
#include <stdint.h>

// ---------------- problem-size maxima (fixed instance: T=4096,D=1024,F=4096,E=8,k=2)
#define T_MAX    4096
#define E_MAX    8
#define SLOT_MAX 2
#define D_MAX    1024
#define F_MAX    4096
#define RPAD_MAX (T_MAX * SLOT_MAX + E_MAX * 128)   // 9216
#define TILES_MAX (RPAD_MAX / 128)                  // 72

// ---------------- device scratch (static: no allocation anywhere)
__device__ float g_Xg [(size_t)RPAD_MAX * D_MAX];   // gathered tokens (tf32-rounded)
__device__ float g_H  [(size_t)RPAD_MAX * F_MAX];   // hidden (tf32-rounded)
__device__ float g_O  [(size_t)RPAD_MAX * D_MAX];   // expert outputs (fp32)
__device__ int   g_sel [T_MAX * SLOT_MAX];
__device__ float g_wts [T_MAX * SLOT_MAX];
__device__ int   g_pos [T_MAX * SLOT_MAX];
__device__ int   g_count [E_MAX];
__device__ int   g_cursor[E_MAX];
__device__ int   g_off   [E_MAX + 1];
__device__ int   g_tile2e[TILES_MAX];
__device__ int   g_row2tok[RPAD_MAX];

// ---------------- helpers ----------------
__device__ __forceinline__ float tf32r(float x) {
    uint32_t u;
    asm("cvt.rna.tf32.f32 %0, %1;" : "=r"(u) : "f"(x));
    return __uint_as_float(u);
}
__device__ __forceinline__ uint32_t tf32r_u(uint32_t x) {
    uint32_t u;
    asm("cvt.rna.tf32.f32 %0, %1;" : "=r"(u) : "f"(__uint_as_float(x)));
    return u;
}
__device__ __forceinline__ uint32_t smem_u32(const void* p) {
    uint32_t a;
    asm("{ .reg .u64 t; cvta.to.shared.u64 t, %1; cvt.u32.u64 %0, t; }" : "=r"(a) : "l"(p));
    return a;
}
__device__ __forceinline__ void cp16(uint32_t dst, const void* src) {
    asm volatile("cp.async.cg.shared.global [%0], [%1], 16;" :: "r"(dst), "l"(src));
}
#define CP_COMMIT() asm volatile("cp.async.commit_group;" ::: "memory")
#define CP_WAIT1()  asm volatile("cp.async.wait_group 1;" ::: "memory")

__device__ __forceinline__ void mma16n8k8(float c[4],
                                          uint32_t a0, uint32_t a1, uint32_t a2, uint32_t a3,
                                          uint32_t b0, uint32_t b1) {
    asm volatile(
        "mma.sync.aligned.m16n8k8.row.col.f32.tf32.tf32.f32 "
        "{%0,%1,%2,%3}, {%4,%5,%6,%7}, {%8,%9}, {%0,%1,%2,%3};"
        : "+f"(c[0]), "+f"(c[1]), "+f"(c[2]), "+f"(c[3])
        : "r"(a0), "r"(a1), "r"(a2), "r"(a3), "r"(b0), "r"(b1));
}

// ---------------- init ----------------
__global__ void k_init() {
    int i = blockIdx.x * blockDim.x + threadIdx.x;
    if (i < RPAD_MAX)  g_row2tok[i] = -1;
    if (i < TILES_MAX) g_tile2e[i]  = -1;
    if (i < E_MAX)   { g_count[i] = 0; g_cursor[i] = 0; }
}

// ---------------- router ----------------
__global__ void k_router(const float* __restrict__ x, const float* __restrict__ gw,
                         const float* __restrict__ gb, const int* __restrict__ topk_p,
                         int D, int E) {
    int t = blockIdx.x;
    float acc[E_MAX];
    #pragma unroll
    for (int e = 0; e < E_MAX; e++) acc[e] = 0.f;
    const float* xr = x + (size_t)t * D;
    for (int d = threadIdx.x; d < D; d += blockDim.x) {
        float xv = xr[d];
        for (int e = 0; e < E; e++) acc[e] += xv * gw[(size_t)e * D + d];
    }
    __shared__ float sred[E_MAX][8];
    int lane = threadIdx.x & 31, wid = threadIdx.x >> 5;
    for (int e = 0; e < E; e++) {
        float v = acc[e];
        #pragma unroll
        for (int o = 16; o > 0; o >>= 1) v += __shfl_down_sync(0xffffffffu, v, o);
        if (lane == 0) sred[e][wid] = v;
    }
    __syncthreads();
    if (threadIdx.x == 0) {
        int nw = blockDim.x >> 5;
        float logit[E_MAX], mx = -1e30f;
        for (int e = 0; e < E; e++) {
            float s = gb[e];
            for (int w = 0; w < nw; w++) s += sred[e][w];
            logit[e] = s; mx = fmaxf(mx, s);
        }
        float p[E_MAX], Z = 0.f;
        for (int e = 0; e < E; e++) { p[e] = expf(logit[e] - mx); Z += p[e]; }
        float invZ = 1.f / Z;
        for (int e = 0; e < E; e++) p[e] *= invZ;

        int k = topk_p ? *topk_p : 2;
        if (k > SLOT_MAX) k = SLOT_MAX;
        if (k < 1) k = 1;
        bool used[E_MAX];
        for (int e = 0; e < E; e++) used[e] = false;
        float wsum = 0.f;
        int sels[SLOT_MAX]; float wv[SLOT_MAX];
        for (int s = 0; s < k; s++) {
            int best = 0; float bv = -1.f;
            for (int e = 0; e < E; e++)
                if (!used[e] && p[e] > bv) { bv = p[e]; best = e; }  // strict > => lowest idx on tie
            used[best] = true;
            sels[s] = best; wv[s] = bv; wsum += bv;
            atomicAdd(&g_count[best], 1);
        }
        float inv = 1.f / wsum;
        for (int s = 0; s < k; s++) { g_sel[t*SLOT_MAX+s] = sels[s]; g_wts[t*SLOT_MAX+s] = wv[s]*inv; }
        for (int s = k; s < SLOT_MAX; s++) { g_sel[t*SLOT_MAX+s] = -1; g_wts[t*SLOT_MAX+s] = 0.f; }
    }
}

// ---------------- scan ----------------
__global__ void k_scan(int E) {
    if (threadIdx.x != 0 || blockIdx.x != 0) return;
    int off = 0;
    for (int e = 0; e < E; e++) {
        g_off[e] = off;
        int tiles = (g_count[e] + 127) >> 7;
        for (int i = 0; i < tiles; i++) g_tile2e[(off >> 7) + i] = e;
        off += tiles << 7;
    }
    g_off[E] = off;
}

// ---------------- assign ----------------
__global__ void k_assign(int T) {
    int idx = blockIdx.x * blockDim.x + threadIdx.x;
    if (idx >= T * SLOT_MAX) return;
    int t = idx / SLOT_MAX, s = idx % SLOT_MAX;
    int e = g_sel[t * SLOT_MAX + s];
    if (e < 0) { g_pos[t * SLOT_MAX + s] = -1; return; }
    int pos = atomicAdd(&g_cursor[e], 1);
    int row = g_off[e] + pos;
    g_row2tok[row] = t;
    g_pos[t * SLOT_MAX + s] = row;
}

// ---------------- gather (+ tf32 rna rounding) ----------------
__global__ void k_gather(const float* __restrict__ x, int D) {
    int row = blockIdx.x;
    int tok = g_row2tok[row];
    float4* dst = (float4*)(g_Xg + (size_t)row * D);
    if (tok >= 0) {
        const float4* src = (const float4*)(x + (size_t)tok * D);
        for (int c = threadIdx.x; c < (D >> 2); c += blockDim.x) {
            float4 v = src[c];
            v.x = tf32r(v.x); v.y = tf32r(v.y); v.z = tf32r(v.z); v.w = tf32r(v.w);
            dst[c] = v;
        }
    } else {
        float4 z = make_float4(0.f, 0.f, 0.f, 0.f);
        for (int c = threadIdx.x; c < (D >> 2); c += blockDim.x) dst[c] = z;
    }
}

// ---------------- tf32 tensor GEMM: 128x256 CTA tile, 64x64 warp tiles ----------------
// C[128(m) x 256(n) tile] = act(A @ W[e] + bias[e])
// A: [rows,K] K-contig (tf32-pre-rounded), W: [E][K][Ntot] native n-contig (fp32,
// rna-rounded in registers), bias: [E][Ntot], C row stride Ntot.
#define BK  16
#define TSA 20     // A smem row stride: frag addr grp*20+thr -> all 32 banks
#define TSB 264    // B smem row stride: frag addr thr*264+grp ≡ thr*8+grp -> all 32 banks
#define AW  (128 * TSA)                 // uints per A buffer (2560)
#define BW  (BK * TSB)                  // uints per B buffer (4224)
#define SMEM_BYTES ((3 * AW + 3 * BW) * 4)   // 81408

__global__ void __launch_bounds__(256)
k_gemm_mma(const float* __restrict__ Abase, const float* __restrict__ W,
           const float* __restrict__ Ball, float* __restrict__ C,
           int Ntot, int K, int act) {
    int tile_m = blockIdx.y, tile_n = blockIdx.x;
    int e = g_tile2e[tile_m];
    if (e < 0) return;

    const float* A = Abase + (size_t)tile_m * 128 * K;
    const float* B = W + (size_t)e * K * Ntot + (size_t)tile_n * 256;   // [k][n], n-contig

    extern __shared__ uint32_t dsm[];
    uint32_t* As = dsm;                 // [3][128][TSA]
    uint32_t* Bs = dsm + 3 * AW;        // [3][BK][TSB]

    int tid = threadIdx.x, lane = tid & 31, wid = tid >> 5;
    int wm = wid & 1, wn = wid >> 1;    // warp tile 64(m) x 64(n)
    int grp = lane >> 2, thr = lane & 3;

    // staging roles — consecutive 16B per consecutive lane (conflict-free phases)
    // A: 512 segs (128 rows x 4); thread does segs tid, tid+256
    int ar0 = tid >> 2, ac0 = (tid & 3) * 4;            // seg tid
    int ar1 = (tid + 256) >> 2;                         // seg tid+256 (same ac0)
    // B: 1024 segs (16 rows x 64); thread does segs tid + 256*i, i=0..3
    int br0 = tid >> 6, bc0 = (tid & 63) * 4;           // rows advance by 4 per i
    uint32_t aS = smem_u32(As), bS = smem_u32(Bs);

    const float* aP0 = A + (size_t)ar0 * K + ac0;
    const float* aP1 = A + (size_t)ar1 * K + ac0;
    const float* bP0 = B + (size_t)br0 * Ntot + bc0;
    const size_t bRow4 = (size_t)4 * Ntot;

    float acc[4][8][4];
    #pragma unroll
    for (int mf = 0; mf < 4; mf++)
        #pragma unroll
        for (int nf = 0; nf < 8; nf++)
            #pragma unroll
            for (int c = 0; c < 4; c++) acc[mf][nf][c] = 0.f;

    int nk = K / BK;

    // stage chunk kc into buffer b
    auto stage = [&](int kc, int b) {
        uint32_t ad = aS + (uint32_t)(b * AW * 4);
        uint32_t bd = bS + (uint32_t)(b * BW * 4);
        const float* ap = aP0 + kc * BK;
        cp16(ad + (uint32_t)((ar0 * TSA + ac0) * 4), ap);
        cp16(ad + (uint32_t)((ar1 * TSA + ac0) * 4), aP1 + kc * BK);
        const float* bp = bP0 + (size_t)kc * BK * Ntot;
        #pragma unroll
        for (int i = 0; i < 4; i++)
            cp16(bd + (uint32_t)(((br0 + 4 * i) * TSB + bc0) * 4), bp + (size_t)i * bRow4);
    };

    // prologue: stage chunks 0,1
    stage(0, 0); CP_COMMIT();
    if (nk > 1) stage(1, 1);
    CP_COMMIT();

    int buf = 0;
    for (int kc = 0; kc < nk; kc++) {
        CP_WAIT1();                     // chunk kc landed (only kc+1 may be in flight)
        __syncthreads();                // visible to all warps; prior chunk's readers done

        int sb = buf + 2; if (sb >= 3) sb -= 3;
        if (kc + 2 < nk) stage(kc + 2, sb);
        CP_COMMIT();

        const uint32_t* Ab = As + buf * AW;
        const uint32_t* Bb = Bs + buf * BW;
        #pragma unroll
        for (int ks = 0; ks < BK; ks += 8) {
            uint32_t af[4][4], bf[8][2];
            #pragma unroll
            for (int mf = 0; mf < 4; mf++) {
                int m0 = wm * 64 + mf * 16 + grp;
                af[mf][0] = Ab[(m0    ) * TSA + ks + thr    ];
                af[mf][1] = Ab[(m0 + 8) * TSA + ks + thr    ];
                af[mf][2] = Ab[(m0    ) * TSA + ks + thr + 4];
                af[mf][3] = Ab[(m0 + 8) * TSA + ks + thr + 4];
            }
            #pragma unroll
            for (int nf = 0; nf < 8; nf++) {
                int n0 = wn * 64 + nf * 8 + grp;
                bf[nf][0] = tf32r_u(Bb[(ks + thr    ) * TSB + n0]);
                bf[nf][1] = tf32r_u(Bb[(ks + thr + 4) * TSB + n0]);
            }
            #pragma unroll
            for (int mf = 0; mf < 4; mf++)
                #pragma unroll
                for (int nf = 0; nf < 8; nf++)
                    mma16n8k8(acc[mf][nf], af[mf][0], af[mf][1], af[mf][2], af[mf][3],
                              bf[nf][0], bf[nf][1]);
        }
        buf = buf + 1; if (buf == 3) buf = 0;
    }

    // epilogue: bias (+ SiLU + rna), direct float2 stores
    const float* bias = Ball + (size_t)e * Ntot + (size_t)tile_n * 256;
    float* Cb = C + (size_t)tile_m * 128 * Ntot + (size_t)tile_n * 256;
    #pragma unroll
    for (int mf = 0; mf < 4; mf++) {
        #pragma unroll
        for (int nf = 0; nf < 8; nf++) {
            int row = wm * 64 + mf * 16 + grp;
            int col = wn * 64 + nf * 8 + thr * 2;
            float b0 = bias[col], b1 = bias[col + 1];
            float v00 = acc[mf][nf][0] + b0, v01 = acc[mf][nf][1] + b1;
            float v10 = acc[mf][nf][2] + b0, v11 = acc[mf][nf][3] + b1;
            if (act) {
                v00 = tf32r(v00 / (1.f + __expf(-v00)));
                v01 = tf32r(v01 / (1.f + __expf(-v01)));
                v10 = tf32r(v10 / (1.f + __expf(-v10)));
                v11 = tf32r(v11 / (1.f + __expf(-v11)));
            }
            *(float2*)(Cb + (size_t)row * Ntot + col)       = make_float2(v00, v01);
            *(float2*)(Cb + (size_t)(row + 8) * Ntot + col) = make_float2(v10, v11);
        }
    }
}

// ---------------- combine ----------------
__global__ void k_combine(float* __restrict__ out, int D) {
    int t = blockIdx.x;
    int rows[SLOT_MAX]; float ws[SLOT_MAX];
    #pragma unroll
    for (int s = 0; s < SLOT_MAX; s++) { rows[s] = g_pos[t*SLOT_MAX+s]; ws[s] = g_wts[t*SLOT_MAX+s]; }
    float4* dst = (float4*)(out + (size_t)t * D);
    for (int c = threadIdx.x; c < (D >> 2); c += blockDim.x) {
        float4 a = make_float4(0.f, 0.f, 0.f, 0.f);
        #pragma unroll
        for (int s = 0; s < SLOT_MAX; s++) {
            if (rows[s] < 0) continue;
            const float4 v = ((const float4*)(g_O + (size_t)rows[s] * D))[c];
            a.x = fmaf(ws[s], v.x, a.x); a.y = fmaf(ws[s], v.y, a.y);
            a.z = fmaf(ws[s], v.z, a.z); a.w = fmaf(ws[s], v.w, a.w);
        }
        dst[c] = a;
    }
}

// ---------------- launch ----------------
extern "C" void kernel_launch(void* const* d_in, const int* in_sizes, int n_in,
                              void* d_out, int out_size) {
    const float* x    = (const float*)d_in[0];
    const float* gw   = (const float*)d_in[1];
    const float* gb   = (const float*)d_in[2];
    const float* w1   = (const float*)d_in[3];
    const float* b1   = (const float*)d_in[4];
    const float* w2   = (const float*)d_in[5];
    const float* b2   = (const float*)d_in[6];
    const int*   topk = (n_in > 7) ? (const int*)d_in[7] : nullptr;
    float* out = (float*)d_out;

    const int E = in_sizes[2];
    const int D = in_sizes[1] / E;
    const int F = in_sizes[4] / E;
    const int T = in_sizes[0] / D;

    float *Xg = nullptr, *H = nullptr, *O = nullptr;
    cudaGetSymbolAddress((void**)&Xg, g_Xg);
    cudaGetSymbolAddress((void**)&H,  g_H);
    cudaGetSymbolAddress((void**)&O,  g_O);

    cudaFuncSetAttribute(k_gemm_mma, cudaFuncAttributeMaxDynamicSharedMemorySize, SMEM_BYTES);

    k_init<<<(RPAD_MAX + 255) / 256, 256>>>();
    k_router<<<T, 256>>>(x, gw, gb, topk, D, E);
    k_scan<<<1, 32>>>(E);
    k_assign<<<(T * SLOT_MAX + 255) / 256, 256>>>(T);
    k_gather<<<RPAD_MAX, 256>>>(x, D);

    // weights consumed in NATIVE [E][K][N] layout — no transpose pass
    k_gemm_mma<<<dim3(F / 256, TILES_MAX), 256, SMEM_BYTES>>>(Xg, w1, b1, H, F, D, 1);
    k_gemm_mma<<<dim3(D / 256, TILES_MAX), 256, SMEM_BYTES>>>(H, w2, b2, O, D, F, 0);

    k_combine<<<T, 256>>>(out, D);
}